// round 15
// baseline (speedup 1.0000x reference)
#include <cuda_runtime.h>
#include <cuda_fp16.h>
#include <math.h>
#include <stdint.h>

#define TOK   8192
#define EMBD  768
#define DFF2  3072
#define NHEAD 8
#define HD    96
#define SEQ   2048
#define NBATCH 4
#define NQKV  2304

// ---------------- scratch (device globals) ----------------------------------
__device__ __half g_yh[TOK * EMBD];
__device__ __half g_qh[TOK * EMBD];
__device__ __half g_kh[TOK * EMBD];
__device__ __half g_vT[TOK * EMBD];     // [b][h][d][seq]
__device__ __half g_oh[TOK * EMBD];
__device__ __half g_zh[TOK * EMBD];
__device__ __half g_hh[TOK * DFF2];
__device__ float  g_x1[TOK * EMBD];
__device__ __half g_wqkvT[NQKV * EMBD];
__device__ float  g_bqkv[NQKV];
__device__ __half g_woT[EMBD * EMBD];
__device__ __half g_w1T[DFF2 * EMBD];
__device__ __half g_w2T[EMBD * DFF2];

// ---------------- helpers ----------------------------------------------------
__device__ __forceinline__ void cpasync16(uint32_t saddr, const void* gaddr) {
    asm volatile("cp.async.cg.shared.global [%0], [%1], 16;" :: "r"(saddr), "l"(gaddr));
}
#define CP_COMMIT() asm volatile("cp.async.commit_group;" ::: "memory")

__device__ __forceinline__ uint32_t smem_u32(const void* p) {
    uint32_t a;
    asm("{ .reg .u64 t; cvta.to.shared.u64 t, %1; cvt.u32.u64 %0, t; }"
        : "=r"(a) : "l"(p));
    return a;
}

__device__ __forceinline__ void mma_f16(float* c, const uint32_t* a, const uint32_t* b) {
    asm volatile(
        "mma.sync.aligned.m16n8k16.row.col.f32.f16.f16.f32 "
        "{%0,%1,%2,%3}, {%4,%5,%6,%7}, {%8,%9}, {%0,%1,%2,%3};"
        : "+f"(c[0]), "+f"(c[1]), "+f"(c[2]), "+f"(c[3])
        : "r"(a[0]), "r"(a[1]), "r"(a[2]), "r"(a[3]), "r"(b[0]), "r"(b[1]));
}

__device__ __forceinline__ void ldmx4(uint32_t* r, uint32_t saddr) {
    asm volatile("ldmatrix.sync.aligned.m8n8.x4.shared.b16 {%0,%1,%2,%3}, [%4];"
        : "=r"(r[0]), "=r"(r[1]), "=r"(r[2]), "=r"(r[3]) : "r"(saddr));
}

__device__ __forceinline__ uint32_t packh2(float a, float b) {
    __half2 h = __floats2half2_rn(a, b);
    return *(uint32_t*)&h;
}

// ---------------- all weight transposes + bias concat in ONE kernel ----------
__global__ __launch_bounds__(256)
void convT_all(const float* __restrict__ wq, const float* __restrict__ wk,
               const float* __restrict__ wv, const float* __restrict__ wo,
               const float* __restrict__ w1, const float* __restrict__ w2,
               const float* __restrict__ bq, const float* __restrict__ bk,
               const float* __restrict__ bv) {
    const int bid = blockIdx.x;
    const int tx = threadIdx.x, ty = threadIdx.y;
    if (bid >= 6912) {
        const int i = (bid - 6912) * 256 + ty * 32 + tx;
        if (i < EMBD) {
            g_bqkv[i] = bq[i];
            g_bqkv[i + EMBD] = bk[i];
            g_bqkv[i + 2 * EMBD] = bv[i];
        }
        return;
    }
    __shared__ float t[32][33];
    const float* W;
    __half* Wt;
    int K, N, n0, k0;
    if (bid < 2304) {
        const int seg = bid / 576, tl = bid % 576;
        K = EMBD; N = EMBD;
        if (seg == 0)      { W = wq; Wt = g_wqkvT; }
        else if (seg == 1) { W = wk; Wt = g_wqkvT + EMBD * EMBD; }
        else if (seg == 2) { W = wv; Wt = g_wqkvT + 2 * EMBD * EMBD; }
        else               { W = wo; Wt = g_woT; }
        n0 = (tl % 24) * 32; k0 = (tl / 24) * 32;
    } else if (bid < 4608) {
        const int tl = bid - 2304;
        K = EMBD; N = DFF2; W = w1; Wt = g_w1T;
        n0 = (tl % 96) * 32; k0 = (tl / 96) * 32;
    } else {
        const int tl = bid - 4608;
        K = DFF2; N = EMBD; W = w2; Wt = g_w2T;
        n0 = (tl % 24) * 32; k0 = (tl / 24) * 32;
    }
    #pragma unroll
    for (int i = 0; i < 32; i += 8)
        t[ty + i][tx] = W[(long)(k0 + ty + i) * N + n0 + tx];
    __syncthreads();
    #pragma unroll
    for (int i = 0; i < 32; i += 8)
        Wt[(long)(n0 + ty + i) * K + k0 + tx] = __float2half(t[tx][ty + i]);
}

// ---------------- LayerNorm (fp32 in -> fp16 out) ---------------------------
__global__ __launch_bounds__(256)
void ln_kernel(const float* __restrict__ x, const float* __restrict__ g,
               const float* __restrict__ b, __half* __restrict__ y) {
    const int row = blockIdx.x;
    const float* xr = x + (long)row * EMBD;
    const int t = threadIdx.x;
    float v0 = xr[t], v1 = xr[t + 256], v2 = xr[t + 512];
    float s  = v0 + v1 + v2;
    float sq = v0 * v0 + v1 * v1 + v2 * v2;
    #pragma unroll
    for (int o = 16; o; o >>= 1) {
        s  += __shfl_xor_sync(0xffffffffu, s,  o);
        sq += __shfl_xor_sync(0xffffffffu, sq, o);
    }
    __shared__ float sbuf[16];
    const int w = t >> 5, l = t & 31;
    if (l == 0) { sbuf[w] = s; sbuf[w + 8] = sq; }
    __syncthreads();
    float ts = 0.f, tsq = 0.f;
    #pragma unroll
    for (int i = 0; i < 8; i++) { ts += sbuf[i]; tsq += sbuf[8 + i]; }
    const float mu  = ts * (1.0f / EMBD);
    const float var = tsq * (1.0f / EMBD) - mu * mu;
    const float r   = rsqrtf(var + 1e-5f);
    __half* yr = y + (long)row * EMBD;
    yr[t]       = __float2half((v0 - mu) * r * g[t]       + b[t]);
    yr[t + 256] = __float2half((v1 - mu) * r * g[t + 256] + b[t + 256]);
    yr[t + 512] = __float2half((v2 - mu) * r * g[t + 512] + b[t + 512]);
}

// ====== fp16 mma GEMM: CTA 128x128, 4 warps (64x64 warptile), 128 thr ========
// EPI: 0 bias(->h), 1 bias+res(->f32), 2 bias+GELU(->h), 3 QKV split epilogue
#define HGK    64
#define HSTR   72
#define A_HB   (128 * HSTR * 2)
#define B_HB   (128 * HSTR * 2)
#define STG_HB (A_HB + B_HB)
#define NSTG   3
#define GMH_SMEM (NSTG * STG_HB)

__device__ __forceinline__ void ld_stage_h(uint32_t sa,
                                           const __half* __restrict__ A,
                                           const __half* __restrict__ Bt,
                                           int bm, int bn, int K,
                                           int k0, int tid) {
    #pragma unroll
    for (int j = 0; j < 8; j++) {        // A: 1024 chunks / 128 thr
        const int ch = tid + j * 128;
        const int r = ch >> 3, kc = ch & 7;
        cpasync16(sa + (r * HSTR + kc * 8) * 2,
                  A + (long)(bm + r) * K + k0 + kc * 8);
    }
    const uint32_t sb = sa + A_HB;
    #pragma unroll
    for (int j = 0; j < 8; j++) {        // B: 1024 chunks
        const int ch = tid + j * 128;
        const int r = ch >> 3, kc = ch & 7;
        cpasync16(sb + (r * HSTR + kc * 8) * 2,
                  Bt + (long)(bn + r) * K + k0 + kc * 8);
    }
}

template <int EPI>
__global__ __launch_bounds__(128, 2)
void gemm_h(const __half* __restrict__ A, const __half* __restrict__ Bt,
            const float* __restrict__ bias, const float* __restrict__ res,
            void* __restrict__ Cout, int M, int N, int K) {
    extern __shared__ __half smh[];
    const uint32_t sbase = smem_u32(smh);

    const int tid  = threadIdx.x;
    const int lane = tid & 31;
    const int wid  = tid >> 5;           // 0..3
    const int bm = blockIdx.y * 128;
    const int bn = blockIdx.x * 128;
    const int wm = (wid & 1) * 64;
    const int wn = (wid >> 1) * 64;

    const int aRow = wm + (lane & 15);
    const int aK   = (lane >> 4) * 8;
    const int bRow = wn + ((lane >> 4) & 1) * 8 + (lane & 7);
    const int bK   = ((lane >> 3) & 1) * 8;

    float acc[4][8][4];
    #pragma unroll
    for (int mi = 0; mi < 4; mi++)
        #pragma unroll
        for (int ni = 0; ni < 8; ni++)
            #pragma unroll
            for (int u = 0; u < 4; u++) acc[mi][ni][u] = 0.f;

    const int nkt = K / HGK;
    #pragma unroll
    for (int p = 0; p < NSTG - 1; p++) {
        if (p < nkt) ld_stage_h(sbase + p * STG_HB, A, Bt, bm, bn, K, p * HGK, tid);
        CP_COMMIT();
    }

    int bufr = 0, bufw = NSTG - 1;
    for (int kt = 0; kt < nkt; kt++) {
        asm volatile("cp.async.wait_group %0;" :: "n"(NSTG - 2) : "memory");
        __syncthreads();

        const int next = kt + NSTG - 1;
        if (next < nkt)
            ld_stage_h(sbase + bufw * STG_HB, A, Bt, bm, bn, K, next * HGK, tid);
        CP_COMMIT();

        const uint32_t fA_u = sbase + bufr * STG_HB;
        const uint32_t fB_u = fA_u + A_HB;
        #pragma unroll
        for (int ks = 0; ks < 4; ks++) {
            uint32_t af[4][4];
            #pragma unroll
            for (int mi = 0; mi < 4; mi++)
                ldmx4(af[mi], fA_u + ((aRow + mi * 16) * HSTR + ks * 16 + aK) * 2);
            #pragma unroll
            for (int nj = 0; nj < 4; nj++) {
                uint32_t bb[4];
                ldmx4(bb, fB_u + ((bRow + nj * 16) * HSTR + ks * 16 + bK) * 2);
                #pragma unroll
                for (int mi = 0; mi < 4; mi++) {
                    mma_f16(acc[mi][nj * 2 + 0], af[mi], &bb[0]);
                    mma_f16(acc[mi][nj * 2 + 1], af[mi], &bb[2]);
                }
            }
        }
        bufr = (bufr + 1 == NSTG) ? 0 : bufr + 1;
        bufw = (bufw + 1 == NSTG) ? 0 : bufw + 1;
    }

    const int erow = bm + wm + (lane >> 2);
    const int ecol = bn + wn + (lane & 3) * 2;
    #pragma unroll
    for (int mi = 0; mi < 4; mi++) {
        #pragma unroll
        for (int half = 0; half < 2; half++) {
            const long r = erow + mi * 16 + half * 8;
            #pragma unroll
            for (int ni = 0; ni < 8; ni++) {
                const int c = ecol + ni * 8;
                float v0 = acc[mi][ni][half * 2 + 0] + bias[c];
                float v1 = acc[mi][ni][half * 2 + 1] + bias[c + 1];
                if (EPI == 2) {
                    v0 = 0.5f * v0 * (1.0f + erff(v0 * 0.70710678118654752f));
                    v1 = 0.5f * v1 * (1.0f + erff(v1 * 0.70710678118654752f));
                }
                if (EPI == 1) {
                    v0 += res[r * N + c];
                    v1 += res[r * N + c + 1];
                }
                if (EPI == 3) {
                    if (c < EMBD) {
                        *(__half2*)&g_qh[r * EMBD + c] = __floats2half2_rn(v0, v1);
                    } else if (c < 2 * EMBD) {
                        *(__half2*)&g_kh[r * EMBD + c - EMBD] = __floats2half2_rn(v0, v1);
                    } else {
                        const int cc = c - 2 * EMBD;
                        const int bb2 = (int)(r >> 11), srow = (int)(r & 2047);
                        g_vT[((long)(bb2 * NHEAD + cc / HD) * HD + (cc % HD)) * SEQ + srow] = __float2half(v0);
                        g_vT[((long)(bb2 * NHEAD + (cc + 1) / HD) * HD + ((cc + 1) % HD)) * SEQ + srow] = __float2half(v1);
                    }
                } else if (EPI == 1) {
                    *(float2*)((float*)Cout + r * N + c) = make_float2(v0, v1);
                } else {
                    *(__half2*)((__half*)Cout + r * N + c) = __floats2half2_rn(v0, v1);
                }
            }
        }
    }
}

// ====== fp16 flash attention: 4 warps x 32 q-rows, 128 thr, 3-stage =========
#define FBM    128
#define FBN    64
#define QSTR_H 104
#define KSTR_H 104
#define VSTR_H 72
#define ANST   3
#define SQ_H   (FBM * QSTR_H)
#define KV_H   (FBN * KSTR_H + HD * VSTR_H)
#define ATT_SMEM ((SQ_H + ANST * KV_H) * 2)

__device__ __forceinline__ void attn_ld_kv_h(uint32_t sk, uint32_t sv,
                                             const __half* __restrict__ K,
                                             const __half* __restrict__ VT,
                                             long baseKV, long baseVT,
                                             int kt, int tid) {
    #pragma unroll
    for (int j = 0; j < 6; j++) {
        const int ch = tid + j * 128;
        const int r = ch / 12, c = ch % 12;
        cpasync16(sk + (r * KSTR_H + c * 8) * 2,
                  K + baseKV + (long)(kt * FBN + r) * EMBD + c * 8);
    }
    #pragma unroll
    for (int j = 0; j < 6; j++) {
        const int ch = tid + j * 128;
        const int d = ch >> 3, sc = ch & 7;
        cpasync16(sv + (d * VSTR_H + sc * 8) * 2,
                  VT + baseVT + (long)d * SEQ + kt * FBN + sc * 8);
    }
}

__global__ __launch_bounds__(128, 2)
void attn_h(const __half* __restrict__ Q, const __half* __restrict__ K,
            const __half* __restrict__ VT, __half* __restrict__ O) {
    extern __shared__ __half smh[];
    __half* sQ = smh;
    __half* sKV = sQ + SQ_H;
    const uint32_t sQ_u  = smem_u32(sQ);
    const uint32_t skv_u = smem_u32(sKV);

    const int b  = blockIdx.z;
    const int h  = blockIdx.y;
    const int qt = blockIdx.x;
    const int tid  = threadIdx.x;
    const int lane = tid & 31;
    const int wid  = tid >> 5;

    const long baseQ  = ((long)(b * SEQ + qt * FBM)) * EMBD + h * HD;
    const long baseKV = ((long)(b * SEQ)) * EMBD + h * HD;
    const long baseVT = (long)(b * NHEAD + h) * HD * SEQ;

    for (int i = tid; i < FBM * 12; i += 128) {
        const int r = i / 12, c = i % 12;
        cpasync16(sQ_u + (r * QSTR_H + c * 8) * 2,
                  Q + baseQ + (long)r * EMBD + c * 8);
    }
    attn_ld_kv_h(skv_u, skv_u + FBN * KSTR_H * 2, K, VT, baseKV, baseVT, 0, tid);
    CP_COMMIT();
    attn_ld_kv_h(skv_u + KV_H * 2, skv_u + (KV_H + FBN * KSTR_H) * 2,
                 K, VT, baseKV, baseVT, 1, tid);
    CP_COMMIT();

    const int aRow = wid * 32 + (lane & 15);
    const int aK   = (lane >> 4) * 8;
    const int bRow = ((lane >> 4) & 1) * 8 + (lane & 7);
    const int bK   = ((lane >> 3) & 1) * 8;
    const int rA = wid * 32 + (lane >> 2);

    float m0[2] = {-1e30f, -1e30f}, m1[2] = {-1e30f, -1e30f};
    float l0[2] = {0.f, 0.f}, l1[2] = {0.f, 0.f};
    float oa[2][12][4];
    #pragma unroll
    for (int mi = 0; mi < 2; mi++)
        #pragma unroll
        for (int nf = 0; nf < 12; nf++)
            #pragma unroll
            for (int u = 0; u < 4; u++) oa[mi][nf][u] = 0.f;

    const int NIT = SEQ / FBN;
    int bufr = 0, bufw = ANST - 1;
    for (int it = 0; it < NIT; it++) {
        asm volatile("cp.async.wait_group 1;" ::: "memory");
        __syncthreads();

        if (it + 2 < NIT) {
            const uint32_t sn = skv_u + bufw * KV_H * 2;
            attn_ld_kv_h(sn, sn + FBN * KSTR_H * 2, K, VT, baseKV, baseVT, it + 2, tid);
        }
        CP_COMMIT();

        const uint32_t fK_u = skv_u + bufr * KV_H * 2;
        const uint32_t fV_u = fK_u + FBN * KSTR_H * 2;

        float sc[2][8][4];
        #pragma unroll
        for (int mi = 0; mi < 2; mi++)
            #pragma unroll
            for (int nf = 0; nf < 8; nf++)
                #pragma unroll
                for (int u = 0; u < 4; u++) sc[mi][nf][u] = 0.f;

        #pragma unroll
        for (int ks = 0; ks < 6; ks++) {
            uint32_t af[2][4];
            #pragma unroll
            for (int mi = 0; mi < 2; mi++)
                ldmx4(af[mi], sQ_u + ((aRow + mi * 16) * QSTR_H + ks * 16 + aK) * 2);
            #pragma unroll
            for (int nj = 0; nj < 4; nj++) {
                uint32_t bb[4];
                ldmx4(bb, fK_u + ((bRow + nj * 16) * KSTR_H + ks * 16 + bK) * 2);
                #pragma unroll
                for (int mi = 0; mi < 2; mi++) {
                    mma_f16(sc[mi][nj * 2 + 0], af[mi], &bb[0]);
                    mma_f16(sc[mi][nj * 2 + 1], af[mi], &bb[2]);
                }
            }
        }

        uint32_t paf[2][4][4];
        #pragma unroll
        for (int mi = 0; mi < 2; mi++) {
            float t0 = -1e30f, t1 = -1e30f;
            #pragma unroll
            for (int nf = 0; nf < 8; nf++) {
                t0 = fmaxf(t0, fmaxf(sc[mi][nf][0], sc[mi][nf][1]));
                t1 = fmaxf(t1, fmaxf(sc[mi][nf][2], sc[mi][nf][3]));
            }
            t0 = fmaxf(t0, __shfl_xor_sync(0xffffffffu, t0, 1));
            t0 = fmaxf(t0, __shfl_xor_sync(0xffffffffu, t0, 2));
            t1 = fmaxf(t1, __shfl_xor_sync(0xffffffffu, t1, 1));
            t1 = fmaxf(t1, __shfl_xor_sync(0xffffffffu, t1, 2));
            const float mn0 = fmaxf(m0[mi], t0), mn1 = fmaxf(m1[mi], t1);
            const float cr0 = __expf(m0[mi] - mn0), cr1 = __expf(m1[mi] - mn1);
            float rs0 = 0.f, rs1 = 0.f;
            #pragma unroll
            for (int nf = 0; nf < 8; nf++) {
                const float p00 = __expf(sc[mi][nf][0] - mn0);
                const float p01 = __expf(sc[mi][nf][1] - mn0);
                const float p10 = __expf(sc[mi][nf][2] - mn1);
                const float p11 = __expf(sc[mi][nf][3] - mn1);
                rs0 += p00 + p01; rs1 += p10 + p11;
                const int j = nf >> 1, hi = (nf & 1) * 2;
                paf[mi][j][hi + 0] = packh2(p00, p01);
                paf[mi][j][hi + 1] = packh2(p10, p11);
            }
            rs0 += __shfl_xor_sync(0xffffffffu, rs0, 1);
            rs0 += __shfl_xor_sync(0xffffffffu, rs0, 2);
            rs1 += __shfl_xor_sync(0xffffffffu, rs1, 1);
            rs1 += __shfl_xor_sync(0xffffffffu, rs1, 2);
            l0[mi] = l0[mi] * cr0 + rs0; m0[mi] = mn0;
            l1[mi] = l1[mi] * cr1 + rs1; m1[mi] = mn1;
            #pragma unroll
            for (int nf = 0; nf < 12; nf++) {
                oa[mi][nf][0] *= cr0; oa[mi][nf][1] *= cr0;
                oa[mi][nf][2] *= cr1; oa[mi][nf][3] *= cr1;
            }
        }

        #pragma unroll
        for (int ks = 0; ks < 4; ks++) {
            #pragma unroll
            for (int nj = 0; nj < 6; nj++) {
                uint32_t bb[4];
                ldmx4(bb, fV_u + ((bRow + nj * 16) * VSTR_H + ks * 16 + bK) * 2);
                #pragma unroll
                for (int mi = 0; mi < 2; mi++) {
                    mma_f16(oa[mi][nj * 2 + 0], paf[mi][ks], &bb[0]);
                    mma_f16(oa[mi][nj * 2 + 1], paf[mi][ks], &bb[2]);
                }
            }
        }

        bufr = (bufr + 1 == ANST) ? 0 : bufr + 1;
        bufw = (bufw + 1 == ANST) ? 0 : bufw + 1;
    }

    #pragma unroll
    for (int mi = 0; mi < 2; mi++) {
        const float s0 = 1.0f / (l0[mi] * 27.712812921102035f);
        const float s1 = 1.0f / (l1[mi] * 27.712812921102035f);
        const long r0 = rA + mi * 16;
        #pragma unroll
        for (int nf = 0; nf < 12; nf++) {
            const int col = nf * 8 + (lane & 3) * 2;
            *(__half2*)(O + baseQ + r0 * EMBD + col) =
                __floats2half2_rn(oa[mi][nf][0] * s0, oa[mi][nf][1] * s0);
            *(__half2*)(O + baseQ + (r0 + 8) * EMBD + col) =
                __floats2half2_rn(oa[mi][nf][2] * s1, oa[mi][nf][3] * s1);
        }
    }
}

// ---------------- launch ----------------------------------------------------
extern "C" void kernel_launch(void* const* d_in, const int* in_sizes, int n_in,
                              void* d_out, int out_size) {
    const float* x     = (const float*)d_in[0];
    const float* ln1_g = (const float*)d_in[1];
    const float* ln1_b = (const float*)d_in[2];
    const float* wq    = (const float*)d_in[3];
    const float* bq    = (const float*)d_in[4];
    const float* wk    = (const float*)d_in[5];
    const float* bk    = (const float*)d_in[6];
    const float* wv    = (const float*)d_in[7];
    const float* bv    = (const float*)d_in[8];
    const float* wo    = (const float*)d_in[9];
    const float* bo    = (const float*)d_in[10];
    const float* ln2_g = (const float*)d_in[11];
    const float* ln2_b = (const float*)d_in[12];
    const float* w1    = (const float*)d_in[13];
    const float* b1    = (const float*)d_in[14];
    const float* w2    = (const float*)d_in[15];
    const float* b2    = (const float*)d_in[16];

    __half *yh, *qh, *kh, *vT, *oh, *zh, *hh, *wqkvT, *woT, *w1T, *w2T;
    float *x1, *bqkv;
    cudaGetSymbolAddress((void**)&yh,    g_yh);
    cudaGetSymbolAddress((void**)&qh,    g_qh);
    cudaGetSymbolAddress((void**)&kh,    g_kh);
    cudaGetSymbolAddress((void**)&vT,    g_vT);
    cudaGetSymbolAddress((void**)&oh,    g_oh);
    cudaGetSymbolAddress((void**)&zh,    g_zh);
    cudaGetSymbolAddress((void**)&hh,    g_hh);
    cudaGetSymbolAddress((void**)&x1,    g_x1);
    cudaGetSymbolAddress((void**)&wqkvT, g_wqkvT);
    cudaGetSymbolAddress((void**)&bqkv,  g_bqkv);
    cudaGetSymbolAddress((void**)&woT,   g_woT);
    cudaGetSymbolAddress((void**)&w1T,   g_w1T);
    cudaGetSymbolAddress((void**)&w2T,   g_w2T);

    cudaFuncSetAttribute(attn_h,
                         cudaFuncAttributeMaxDynamicSharedMemorySize, ATT_SMEM);
    cudaFuncSetAttribute(gemm_h<1>,
                         cudaFuncAttributeMaxDynamicSharedMemorySize, GMH_SMEM);
    cudaFuncSetAttribute(gemm_h<2>,
                         cudaFuncAttributeMaxDynamicSharedMemorySize, GMH_SMEM);
    cudaFuncSetAttribute(gemm_h<3>,
                         cudaFuncAttributeMaxDynamicSharedMemorySize, GMH_SMEM);

    convT_all<<<6915, dim3(32, 8)>>>(wq, wk, wv, wo, w1, w2, bq, bk, bv);

    // LN1
    ln_kernel<<<TOK, 256>>>(x, ln1_g, ln1_b, yh);
    // fused QKV projection
    gemm_h<3><<<dim3(NQKV / 128, TOK / 128), 128, GMH_SMEM>>>(yh, wqkvT, bqkv, nullptr, nullptr, TOK, NQKV, EMBD);
    // attention (4 warps x 32 rows)
    attn_h<<<dim3(SEQ / FBM, NHEAD, NBATCH), 128, ATT_SMEM>>>(qh, kh, vT, oh);
    // output projection + residual (fp32 out)
    gemm_h<1><<<dim3(EMBD / 128, TOK / 128), 128, GMH_SMEM>>>(oh, woT, bo, x, x1, TOK, EMBD, EMBD);
    // LN2
    ln_kernel<<<TOK, 256>>>(x1, ln2_g, ln2_b, zh);
    // FFN
    gemm_h<2><<<dim3(DFF2 / 128, TOK / 128), 128, GMH_SMEM>>>(zh, w1T, b1, nullptr, hh, TOK, DFF2, EMBD);
    gemm_h<1><<<dim3(EMBD / 128, TOK / 128), 128, GMH_SMEM>>>(hh, w2T, b2, x1, (float*)d_out, TOK, EMBD, DFF2);
}

// round 16
// speedup vs baseline: 1.1101x; 1.1101x over previous
#include <cuda_runtime.h>
#include <cuda_fp16.h>
#include <math.h>
#include <stdint.h>

#define TOK   8192
#define EMBD  768
#define DFF2  3072
#define NHEAD 8
#define HD    96
#define SEQ   2048
#define NBATCH 4
#define NQKV  2304

// ---------------- scratch (device globals) ----------------------------------
__device__ __half g_yh[TOK * EMBD];
__device__ __half g_qh[TOK * EMBD];
__device__ __half g_kh[TOK * EMBD];
__device__ __half g_vT[TOK * EMBD];     // [b][h][d][seq]
__device__ __half g_oh[TOK * EMBD];
__device__ __half g_zh[TOK * EMBD];
__device__ __half g_hh[TOK * DFF2];
__device__ float  g_x1[TOK * EMBD];
__device__ __half g_wqkvT[NQKV * EMBD];
__device__ float  g_bqkv[NQKV];
__device__ __half g_woT[EMBD * EMBD];
__device__ __half g_w1T[DFF2 * EMBD];
__device__ __half g_w2T[EMBD * DFF2];

// ---------------- helpers ----------------------------------------------------
__device__ __forceinline__ void cpasync16(uint32_t saddr, const void* gaddr) {
    asm volatile("cp.async.cg.shared.global [%0], [%1], 16;" :: "r"(saddr), "l"(gaddr));
}
#define CP_COMMIT() asm volatile("cp.async.commit_group;" ::: "memory")

__device__ __forceinline__ uint32_t smem_u32(const void* p) {
    uint32_t a;
    asm("{ .reg .u64 t; cvta.to.shared.u64 t, %1; cvt.u32.u64 %0, t; }"
        : "=r"(a) : "l"(p));
    return a;
}

__device__ __forceinline__ void mma_f16(float* c, const uint32_t* a, const uint32_t* b) {
    asm volatile(
        "mma.sync.aligned.m16n8k16.row.col.f32.f16.f16.f32 "
        "{%0,%1,%2,%3}, {%4,%5,%6,%7}, {%8,%9}, {%0,%1,%2,%3};"
        : "+f"(c[0]), "+f"(c[1]), "+f"(c[2]), "+f"(c[3])
        : "r"(a[0]), "r"(a[1]), "r"(a[2]), "r"(a[3]), "r"(b[0]), "r"(b[1]));
}

__device__ __forceinline__ void ldmx4(uint32_t* r, uint32_t saddr) {
    asm volatile("ldmatrix.sync.aligned.m8n8.x4.shared.b16 {%0,%1,%2,%3}, [%4];"
        : "=r"(r[0]), "=r"(r[1]), "=r"(r[2]), "=r"(r[3]) : "r"(saddr));
}

__device__ __forceinline__ uint32_t packh2(float a, float b) {
    __half2 h = __floats2half2_rn(a, b);
    return *(uint32_t*)&h;
}

// ---- weight transposes + bias concat + LN1 fused into ONE launch ----------
// blocks [0,6912): transposes; [6912,6915): bias concat; [6915,6915+TOK): LN1
__global__ __launch_bounds__(256)
void convT_all(const float* __restrict__ wq, const float* __restrict__ wk,
               const float* __restrict__ wv, const float* __restrict__ wo,
               const float* __restrict__ w1, const float* __restrict__ w2,
               const float* __restrict__ bq, const float* __restrict__ bk,
               const float* __restrict__ bv,
               const float* __restrict__ x,  const float* __restrict__ ln1_g,
               const float* __restrict__ ln1_b) {
    const int bid = blockIdx.x;
    const int tx = threadIdx.x, ty = threadIdx.y;   // 32 x 8
    const int t  = ty * 32 + tx;

    if (bid >= 6915) {
        // ---- LN1 row ----
        const int row = bid - 6915;
        const float* xr = x + (long)row * EMBD;
        float v0 = xr[t], v1 = xr[t + 256], v2 = xr[t + 512];
        float s  = v0 + v1 + v2;
        float sq = v0 * v0 + v1 * v1 + v2 * v2;
        #pragma unroll
        for (int o = 16; o; o >>= 1) {
            s  += __shfl_xor_sync(0xffffffffu, s,  o);
            sq += __shfl_xor_sync(0xffffffffu, sq, o);
        }
        __shared__ float sbuf[16];
        if (tx == 0) { sbuf[ty] = s; sbuf[ty + 8] = sq; }
        __syncthreads();
        float ts = 0.f, tsq = 0.f;
        #pragma unroll
        for (int i = 0; i < 8; i++) { ts += sbuf[i]; tsq += sbuf[8 + i]; }
        const float mu  = ts * (1.0f / EMBD);
        const float var = tsq * (1.0f / EMBD) - mu * mu;
        const float r   = rsqrtf(var + 1e-5f);
        __half* yr = g_yh + (long)row * EMBD;
        yr[t]       = __float2half((v0 - mu) * r * ln1_g[t]       + ln1_b[t]);
        yr[t + 256] = __float2half((v1 - mu) * r * ln1_g[t + 256] + ln1_b[t + 256]);
        yr[t + 512] = __float2half((v2 - mu) * r * ln1_g[t + 512] + ln1_b[t + 512]);
        return;
    }
    if (bid >= 6912) {
        const int i = (bid - 6912) * 256 + t;
        if (i < EMBD) {
            g_bqkv[i] = bq[i];
            g_bqkv[i + EMBD] = bk[i];
            g_bqkv[i + 2 * EMBD] = bv[i];
        }
        return;
    }
    __shared__ float tbuf[32][33];
    const float* W;
    __half* Wt;
    int K, N, n0, k0;
    if (bid < 2304) {
        const int seg = bid / 576, tl = bid % 576;
        K = EMBD; N = EMBD;
        if (seg == 0)      { W = wq; Wt = g_wqkvT; }
        else if (seg == 1) { W = wk; Wt = g_wqkvT + EMBD * EMBD; }
        else if (seg == 2) { W = wv; Wt = g_wqkvT + 2 * EMBD * EMBD; }
        else               { W = wo; Wt = g_woT; }
        n0 = (tl % 24) * 32; k0 = (tl / 24) * 32;
    } else if (bid < 4608) {
        const int tl = bid - 2304;
        K = EMBD; N = DFF2; W = w1; Wt = g_w1T;
        n0 = (tl % 96) * 32; k0 = (tl / 96) * 32;
    } else {
        const int tl = bid - 4608;
        K = DFF2; N = EMBD; W = w2; Wt = g_w2T;
        n0 = (tl % 24) * 32; k0 = (tl / 24) * 32;
    }
    #pragma unroll
    for (int i = 0; i < 32; i += 8)
        tbuf[ty + i][tx] = W[(long)(k0 + ty + i) * N + n0 + tx];
    __syncthreads();
    #pragma unroll
    for (int i = 0; i < 32; i += 8)
        Wt[(long)(n0 + ty + i) * K + k0 + tx] = __float2half(tbuf[tx][ty + i]);
}

// ---------------- LayerNorm (fp32 in -> fp16 out), for LN2 ------------------
__global__ __launch_bounds__(256)
void ln_kernel(const float* __restrict__ x, const float* __restrict__ g,
               const float* __restrict__ b, __half* __restrict__ y) {
    const int row = blockIdx.x;
    const float* xr = x + (long)row * EMBD;
    const int t = threadIdx.x;
    float v0 = xr[t], v1 = xr[t + 256], v2 = xr[t + 512];
    float s  = v0 + v1 + v2;
    float sq = v0 * v0 + v1 * v1 + v2 * v2;
    #pragma unroll
    for (int o = 16; o; o >>= 1) {
        s  += __shfl_xor_sync(0xffffffffu, s,  o);
        sq += __shfl_xor_sync(0xffffffffu, sq, o);
    }
    __shared__ float sbuf[16];
    const int w = t >> 5, l = t & 31;
    if (l == 0) { sbuf[w] = s; sbuf[w + 8] = sq; }
    __syncthreads();
    float ts = 0.f, tsq = 0.f;
    #pragma unroll
    for (int i = 0; i < 8; i++) { ts += sbuf[i]; tsq += sbuf[8 + i]; }
    const float mu  = ts * (1.0f / EMBD);
    const float var = tsq * (1.0f / EMBD) - mu * mu;
    const float r   = rsqrtf(var + 1e-5f);
    __half* yr = y + (long)row * EMBD;
    yr[t]       = __float2half((v0 - mu) * r * g[t]       + b[t]);
    yr[t + 256] = __float2half((v1 - mu) * r * g[t + 256] + b[t + 256]);
    yr[t + 512] = __float2half((v2 - mu) * r * g[t + 512] + b[t + 512]);
}

// ====== fp16 mma GEMM: CTA tile 128x128, 8 warps (32x64 warptile) ===========
// EPI: 0 bias(->h), 1 bias+res(->f32), 2 bias+GELU(->h), 3 QKV split epilogue
#define HGK    64
#define HSTR   72
#define A_HB   (128 * HSTR * 2)
#define B_HB   (128 * HSTR * 2)
#define STG_HB (A_HB + B_HB)
#define NSTG   3
#define GMH_SMEM (NSTG * STG_HB)

__device__ __forceinline__ void ld_stage_h(uint32_t sa,
                                           const __half* __restrict__ A,
                                           const __half* __restrict__ Bt,
                                           int bm, int bn, int K,
                                           int k0, int tid) {
    #pragma unroll
    for (int j = 0; j < 4; j++) {
        const int ch = tid + j * 256;
        const int r = ch >> 3, kc = ch & 7;
        cpasync16(sa + (r * HSTR + kc * 8) * 2,
                  A + (long)(bm + r) * K + k0 + kc * 8);
    }
    const uint32_t sb = sa + A_HB;
    #pragma unroll
    for (int j = 0; j < 4; j++) {
        const int ch = tid + j * 256;
        const int r = ch >> 3, kc = ch & 7;
        cpasync16(sb + (r * HSTR + kc * 8) * 2,
                  Bt + (long)(bn + r) * K + k0 + kc * 8);
    }
}

template <int EPI>
__global__ __launch_bounds__(256, 2)
void gemm_h(const __half* __restrict__ A, const __half* __restrict__ Bt,
            const float* __restrict__ bias, const float* __restrict__ res,
            void* __restrict__ Cout, int M, int N, int K) {
    extern __shared__ __half smh[];
    const uint32_t sbase = smem_u32(smh);

    const int tid  = threadIdx.x;
    const int lane = tid & 31;
    const int wid  = tid >> 5;
    const int bm = blockIdx.y * 128;
    const int bn = blockIdx.x * 128;
    const int wm = (wid & 3) * 32;
    const int wn = (wid >> 2) * 64;

    const int aRow = wm + (lane & 15);
    const int aK   = (lane >> 4) * 8;
    const int bRow = wn + ((lane >> 4) & 1) * 8 + (lane & 7);
    const int bK   = ((lane >> 3) & 1) * 8;

    float acc[2][8][4];
    #pragma unroll
    for (int mi = 0; mi < 2; mi++)
        #pragma unroll
        for (int ni = 0; ni < 8; ni++)
            #pragma unroll
            for (int u = 0; u < 4; u++) acc[mi][ni][u] = 0.f;

    const int nkt = K / HGK;
    #pragma unroll
    for (int p = 0; p < NSTG - 1; p++) {
        if (p < nkt) ld_stage_h(sbase + p * STG_HB, A, Bt, bm, bn, K, p * HGK, tid);
        CP_COMMIT();
    }

    int bufr = 0, bufw = NSTG - 1;
    for (int kt = 0; kt < nkt; kt++) {
        asm volatile("cp.async.wait_group %0;" :: "n"(NSTG - 2) : "memory");
        __syncthreads();

        const int next = kt + NSTG - 1;
        if (next < nkt)
            ld_stage_h(sbase + bufw * STG_HB, A, Bt, bm, bn, K, next * HGK, tid);
        CP_COMMIT();

        const uint32_t fA_u = sbase + bufr * STG_HB;
        const uint32_t fB_u = fA_u + A_HB;
        #pragma unroll
        for (int ks = 0; ks < 4; ks++) {
            uint32_t af[2][4];
            #pragma unroll
            for (int mi = 0; mi < 2; mi++)
                ldmx4(af[mi], fA_u + ((aRow + mi * 16) * HSTR + ks * 16 + aK) * 2);
            #pragma unroll
            for (int nj = 0; nj < 4; nj++) {
                uint32_t bb[4];
                ldmx4(bb, fB_u + ((bRow + nj * 16) * HSTR + ks * 16 + bK) * 2);
                #pragma unroll
                for (int mi = 0; mi < 2; mi++) {
                    mma_f16(acc[mi][nj * 2 + 0], af[mi], &bb[0]);
                    mma_f16(acc[mi][nj * 2 + 1], af[mi], &bb[2]);
                }
            }
        }
        bufr = (bufr + 1 == NSTG) ? 0 : bufr + 1;
        bufw = (bufw + 1 == NSTG) ? 0 : bufw + 1;
    }

    const int erow = bm + wm + (lane >> 2);
    const int ecol = bn + wn + (lane & 3) * 2;
    #pragma unroll
    for (int mi = 0; mi < 2; mi++) {
        #pragma unroll
        for (int half = 0; half < 2; half++) {
            const long r = erow + mi * 16 + half * 8;
            #pragma unroll
            for (int ni = 0; ni < 8; ni++) {
                const int c = ecol + ni * 8;
                float v0 = acc[mi][ni][half * 2 + 0] + bias[c];
                float v1 = acc[mi][ni][half * 2 + 1] + bias[c + 1];
                if (EPI == 2) {
                    v0 = 0.5f * v0 * (1.0f + erff(v0 * 0.70710678118654752f));
                    v1 = 0.5f * v1 * (1.0f + erff(v1 * 0.70710678118654752f));
                }
                if (EPI == 1) {
                    v0 += res[r * N + c];
                    v1 += res[r * N + c + 1];
                }
                if (EPI == 3) {
                    if (c < EMBD) {
                        *(__half2*)&g_qh[r * EMBD + c] = __floats2half2_rn(v0, v1);
                    } else if (c < 2 * EMBD) {
                        *(__half2*)&g_kh[r * EMBD + c - EMBD] = __floats2half2_rn(v0, v1);
                    } else {
                        const int cc = c - 2 * EMBD;
                        const int bb2 = (int)(r >> 11), srow = (int)(r & 2047);
                        g_vT[((long)(bb2 * NHEAD + cc / HD) * HD + (cc % HD)) * SEQ + srow] = __float2half(v0);
                        g_vT[((long)(bb2 * NHEAD + (cc + 1) / HD) * HD + ((cc + 1) % HD)) * SEQ + srow] = __float2half(v1);
                    }
                } else if (EPI == 1) {
                    *(float2*)((float*)Cout + r * N + c) = make_float2(v0, v1);
                } else {
                    *(__half2*)((__half*)Cout + r * N + c) = __floats2half2_rn(v0, v1);
                }
            }
        }
    }
}

// ====== fp16 flash attention: 4 warps x 32 q-rows, 128 thr, 3-stage =========
#define FBM    128
#define FBN    64
#define QSTR_H 104
#define KSTR_H 104
#define VSTR_H 72
#define ANST   3
#define SQ_H   (FBM * QSTR_H)
#define KV_H   (FBN * KSTR_H + HD * VSTR_H)
#define ATT_SMEM ((SQ_H + ANST * KV_H) * 2)

__device__ __forceinline__ void attn_ld_kv_h(uint32_t sk, uint32_t sv,
                                             const __half* __restrict__ K,
                                             const __half* __restrict__ VT,
                                             long baseKV, long baseVT,
                                             int kt, int tid) {
    #pragma unroll
    for (int j = 0; j < 6; j++) {
        const int ch = tid + j * 128;
        const int r = ch / 12, c = ch % 12;
        cpasync16(sk + (r * KSTR_H + c * 8) * 2,
                  K + baseKV + (long)(kt * FBN + r) * EMBD + c * 8);
    }
    #pragma unroll
    for (int j = 0; j < 6; j++) {
        const int ch = tid + j * 128;
        const int d = ch >> 3, sc = ch & 7;
        cpasync16(sv + (d * VSTR_H + sc * 8) * 2,
                  VT + baseVT + (long)d * SEQ + kt * FBN + sc * 8);
    }
}

__global__ __launch_bounds__(128, 2)
void attn_h(const __half* __restrict__ Q, const __half* __restrict__ K,
            const __half* __restrict__ VT, __half* __restrict__ O) {
    extern __shared__ __half smh[];
    __half* sQ = smh;
    __half* sKV = sQ + SQ_H;
    const uint32_t sQ_u  = smem_u32(sQ);
    const uint32_t skv_u = smem_u32(sKV);

    const int b  = blockIdx.z;
    const int h  = blockIdx.y;
    const int qt = blockIdx.x;
    const int tid  = threadIdx.x;
    const int lane = tid & 31;
    const int wid  = tid >> 5;

    const long baseQ  = ((long)(b * SEQ + qt * FBM)) * EMBD + h * HD;
    const long baseKV = ((long)(b * SEQ)) * EMBD + h * HD;
    const long baseVT = (long)(b * NHEAD + h) * HD * SEQ;

    for (int i = tid; i < FBM * 12; i += 128) {
        const int r = i / 12, c = i % 12;
        cpasync16(sQ_u + (r * QSTR_H + c * 8) * 2,
                  Q + baseQ + (long)r * EMBD + c * 8);
    }
    attn_ld_kv_h(skv_u, skv_u + FBN * KSTR_H * 2, K, VT, baseKV, baseVT, 0, tid);
    CP_COMMIT();
    attn_ld_kv_h(skv_u + KV_H * 2, skv_u + (KV_H + FBN * KSTR_H) * 2,
                 K, VT, baseKV, baseVT, 1, tid);
    CP_COMMIT();

    const int aRow = wid * 32 + (lane & 15);
    const int aK   = (lane >> 4) * 8;
    const int bRow = ((lane >> 4) & 1) * 8 + (lane & 7);
    const int bK   = ((lane >> 3) & 1) * 8;
    const int rA = wid * 32 + (lane >> 2);

    float m0[2] = {-1e30f, -1e30f}, m1[2] = {-1e30f, -1e30f};
    float l0[2] = {0.f, 0.f}, l1[2] = {0.f, 0.f};
    float oa[2][12][4];
    #pragma unroll
    for (int mi = 0; mi < 2; mi++)
        #pragma unroll
        for (int nf = 0; nf < 12; nf++)
            #pragma unroll
            for (int u = 0; u < 4; u++) oa[mi][nf][u] = 0.f;

    const int NIT = SEQ / FBN;
    int bufr = 0, bufw = ANST - 1;
    for (int it = 0; it < NIT; it++) {
        asm volatile("cp.async.wait_group 1;" ::: "memory");
        __syncthreads();

        if (it + 2 < NIT) {
            const uint32_t sn = skv_u + bufw * KV_H * 2;
            attn_ld_kv_h(sn, sn + FBN * KSTR_H * 2, K, VT, baseKV, baseVT, it + 2, tid);
        }
        CP_COMMIT();

        const uint32_t fK_u = skv_u + bufr * KV_H * 2;
        const uint32_t fV_u = fK_u + FBN * KSTR_H * 2;

        float sc[2][8][4];
        #pragma unroll
        for (int mi = 0; mi < 2; mi++)
            #pragma unroll
            for (int nf = 0; nf < 8; nf++)
                #pragma unroll
                for (int u = 0; u < 4; u++) sc[mi][nf][u] = 0.f;

        #pragma unroll
        for (int ks = 0; ks < 6; ks++) {
            uint32_t af[2][4];
            #pragma unroll
            for (int mi = 0; mi < 2; mi++)
                ldmx4(af[mi], sQ_u + ((aRow + mi * 16) * QSTR_H + ks * 16 + aK) * 2);
            #pragma unroll
            for (int nj = 0; nj < 4; nj++) {
                uint32_t bb[4];
                ldmx4(bb, fK_u + ((bRow + nj * 16) * KSTR_H + ks * 16 + bK) * 2);
                #pragma unroll
                for (int mi = 0; mi < 2; mi++) {
                    mma_f16(sc[mi][nj * 2 + 0], af[mi], &bb[0]);
                    mma_f16(sc[mi][nj * 2 + 1], af[mi], &bb[2]);
                }
            }
        }

        uint32_t paf[2][4][4];
        #pragma unroll
        for (int mi = 0; mi < 2; mi++) {
            float t0 = -1e30f, t1 = -1e30f;
            #pragma unroll
            for (int nf = 0; nf < 8; nf++) {
                t0 = fmaxf(t0, fmaxf(sc[mi][nf][0], sc[mi][nf][1]));
                t1 = fmaxf(t1, fmaxf(sc[mi][nf][2], sc[mi][nf][3]));
            }
            t0 = fmaxf(t0, __shfl_xor_sync(0xffffffffu, t0, 1));
            t0 = fmaxf(t0, __shfl_xor_sync(0xffffffffu, t0, 2));
            t1 = fmaxf(t1, __shfl_xor_sync(0xffffffffu, t1, 1));
            t1 = fmaxf(t1, __shfl_xor_sync(0xffffffffu, t1, 2));
            const float mn0 = fmaxf(m0[mi], t0), mn1 = fmaxf(m1[mi], t1);
            const float cr0 = __expf(m0[mi] - mn0), cr1 = __expf(m1[mi] - mn1);
            float rs0 = 0.f, rs1 = 0.f;
            #pragma unroll
            for (int nf = 0; nf < 8; nf++) {
                const float p00 = __expf(sc[mi][nf][0] - mn0);
                const float p01 = __expf(sc[mi][nf][1] - mn0);
                const float p10 = __expf(sc[mi][nf][2] - mn1);
                const float p11 = __expf(sc[mi][nf][3] - mn1);
                rs0 += p00 + p01; rs1 += p10 + p11;
                const int j = nf >> 1, hi = (nf & 1) * 2;
                paf[mi][j][hi + 0] = packh2(p00, p01);
                paf[mi][j][hi + 1] = packh2(p10, p11);
            }
            rs0 += __shfl_xor_sync(0xffffffffu, rs0, 1);
            rs0 += __shfl_xor_sync(0xffffffffu, rs0, 2);
            rs1 += __shfl_xor_sync(0xffffffffu, rs1, 1);
            rs1 += __shfl_xor_sync(0xffffffffu, rs1, 2);
            l0[mi] = l0[mi] * cr0 + rs0; m0[mi] = mn0;
            l1[mi] = l1[mi] * cr1 + rs1; m1[mi] = mn1;
            #pragma unroll
            for (int nf = 0; nf < 12; nf++) {
                oa[mi][nf][0] *= cr0; oa[mi][nf][1] *= cr0;
                oa[mi][nf][2] *= cr1; oa[mi][nf][3] *= cr1;
            }
        }

        #pragma unroll
        for (int ks = 0; ks < 4; ks++) {
            #pragma unroll
            for (int nj = 0; nj < 6; nj++) {
                uint32_t bb[4];
                ldmx4(bb, fV_u + ((bRow + nj * 16) * VSTR_H + ks * 16 + bK) * 2);
                #pragma unroll
                for (int mi = 0; mi < 2; mi++) {
                    mma_f16(oa[mi][nj * 2 + 0], paf[mi][ks], &bb[0]);
                    mma_f16(oa[mi][nj * 2 + 1], paf[mi][ks], &bb[2]);
                }
            }
        }

        bufr = (bufr + 1 == ANST) ? 0 : bufr + 1;
        bufw = (bufw + 1 == ANST) ? 0 : bufw + 1;
    }

    #pragma unroll
    for (int mi = 0; mi < 2; mi++) {
        const float s0 = 1.0f / (l0[mi] * 27.712812921102035f);
        const float s1 = 1.0f / (l1[mi] * 27.712812921102035f);
        const long r0 = rA + mi * 16;
        #pragma unroll
        for (int nf = 0; nf < 12; nf++) {
            const int col = nf * 8 + (lane & 3) * 2;
            *(__half2*)(O + baseQ + r0 * EMBD + col) =
                __floats2half2_rn(oa[mi][nf][0] * s0, oa[mi][nf][1] * s0);
            *(__half2*)(O + baseQ + (r0 + 8) * EMBD + col) =
                __floats2half2_rn(oa[mi][nf][2] * s1, oa[mi][nf][3] * s1);
        }
    }
}

// ---------------- launch ----------------------------------------------------
extern "C" void kernel_launch(void* const* d_in, const int* in_sizes, int n_in,
                              void* d_out, int out_size) {
    const float* x     = (const float*)d_in[0];
    const float* ln1_g = (const float*)d_in[1];
    const float* ln1_b = (const float*)d_in[2];
    const float* wq    = (const float*)d_in[3];
    const float* bq    = (const float*)d_in[4];
    const float* wk    = (const float*)d_in[5];
    const float* bk    = (const float*)d_in[6];
    const float* wv    = (const float*)d_in[7];
    const float* bv    = (const float*)d_in[8];
    const float* wo    = (const float*)d_in[9];
    const float* bo    = (const float*)d_in[10];
    const float* ln2_g = (const float*)d_in[11];
    const float* ln2_b = (const float*)d_in[12];
    const float* w1    = (const float*)d_in[13];
    const float* b1    = (const float*)d_in[14];
    const float* w2    = (const float*)d_in[15];
    const float* b2    = (const float*)d_in[16];

    __half *yh, *qh, *kh, *vT, *oh, *zh, *hh, *wqkvT, *woT, *w1T, *w2T;
    float *x1, *bqkv;
    cudaGetSymbolAddress((void**)&yh,    g_yh);
    cudaGetSymbolAddress((void**)&qh,    g_qh);
    cudaGetSymbolAddress((void**)&kh,    g_kh);
    cudaGetSymbolAddress((void**)&vT,    g_vT);
    cudaGetSymbolAddress((void**)&oh,    g_oh);
    cudaGetSymbolAddress((void**)&zh,    g_zh);
    cudaGetSymbolAddress((void**)&hh,    g_hh);
    cudaGetSymbolAddress((void**)&x1,    g_x1);
    cudaGetSymbolAddress((void**)&wqkvT, g_wqkvT);
    cudaGetSymbolAddress((void**)&bqkv,  g_bqkv);
    cudaGetSymbolAddress((void**)&woT,   g_woT);
    cudaGetSymbolAddress((void**)&w1T,   g_w1T);
    cudaGetSymbolAddress((void**)&w2T,   g_w2T);

    cudaFuncSetAttribute(attn_h,
                         cudaFuncAttributeMaxDynamicSharedMemorySize, ATT_SMEM);
    cudaFuncSetAttribute(gemm_h<1>,
                         cudaFuncAttributeMaxDynamicSharedMemorySize, GMH_SMEM);
    cudaFuncSetAttribute(gemm_h<2>,
                         cudaFuncAttributeMaxDynamicSharedMemorySize, GMH_SMEM);
    cudaFuncSetAttribute(gemm_h<3>,
                         cudaFuncAttributeMaxDynamicSharedMemorySize, GMH_SMEM);

    // transposes + bias concat + LN1 all in ONE launch (independent work)
    convT_all<<<6915 + TOK, dim3(32, 8)>>>(wq, wk, wv, wo, w1, w2,
                                           bq, bk, bv, x, ln1_g, ln1_b);

    // fused QKV projection
    gemm_h<3><<<dim3(NQKV / 128, TOK / 128), 256, GMH_SMEM>>>(yh, wqkvT, bqkv, nullptr, nullptr, TOK, NQKV, EMBD);
    // attention (4 warps x 32 rows)
    attn_h<<<dim3(SEQ / FBM, NHEAD, NBATCH), 128, ATT_SMEM>>>(qh, kh, vT, oh);
    // output projection + residual (fp32 out)
    gemm_h<1><<<dim3(EMBD / 128, TOK / 128), 256, GMH_SMEM>>>(oh, woT, bo, x, x1, TOK, EMBD, EMBD);
    // LN2
    ln_kernel<<<TOK, 256>>>(x1, ln2_g, ln2_b, zh);
    // FFN
    gemm_h<2><<<dim3(DFF2 / 128, TOK / 128), 256, GMH_SMEM>>>(zh, w1T, b1, nullptr, hh, TOK, DFF2, EMBD);
    gemm_h<1><<<dim3(EMBD / 128, TOK / 128), 256, GMH_SMEM>>>(hh, w2T, b2, x1, (float*)d_out, TOK, EMBD, DFF2);
}